// round 5
// baseline (speedup 1.0000x reference)
#include <cuda_runtime.h>

#define HH 24
#define WW 24
#define P_ 576
#define B0_ 64
#define B_ 128
#define CIN 256
#define HID 128
#define OUTC 256
#define KNN 9
#define N_NODES (B0_*P_)   // 36864

// ---------------- scratch (static device globals; no allocation) ----------------
__device__ float g_h [N_NODES*256];   // space linear output [N, 2*128]
__device__ float g_as[N_NODES*2];     // per-node attn src logits (2 heads)
__device__ float g_ad[N_NODES*2];     // per-node attn dst logits
__device__ float g_xs[N_NODES*256];   // x_space
__device__ float g_pp [B0_*8*256];    // pool partials [b, chunk, c]
__device__ float g_hv [B0_*256];      // view linear output (64 distinct rows)
__device__ float g_avs[B0_];          // view attn src logits
__device__ float g_avd[B0_];          // view attn dst logits
__device__ float g_feat[B0_*256];     // view GAT output (only first 64 needed)

// ---------------- Kernel A: fused gather-GEMM + attention-logit epilogue --------
// h = node @ W_space, node[n,c] = x[b, c, p] (n = b*576 + p).
// Tiles: 128(M) x 128(N) x 16(K); 256 threads; 8x8 per-thread micro-tile.
// Double-buffered smem staging: LDG for tile t+1 issued before FMA on tile t.
// Each y-block covers exactly one head (cols [0,128) head0, [128,256) head1),
// so per-node attention dots are computed in the epilogue (no extra pass).
__global__ void __launch_bounds__(256, 2)
gemm_space(const float* __restrict__ x, const float* __restrict__ Wm,
           const float* __restrict__ att_src, const float* __restrict__ att_dst) {
    __shared__ float sA[2][16][128];
    __shared__ float sB[2][16][128];
    int tid = threadIdx.x;
    int tx = tid & 15, ty = tid >> 4;
    int rowBase = blockIdx.x * 128;      // 288 blocks
    int colBase = blockIdx.y * 128;      // 2 blocks (== head)

    // A loader: thread owns tile-row lr, k-quadrant lkq (8 k's each)
    int lr  = tid & 127;
    int lkq = tid >> 7;                  // 0/1
    int n_l = rowBase + lr;
    int b_l = n_l / P_;
    int p_l = n_l - b_l * P_;
    const float* xrow = x + (size_t)b_l * (CIN * P_) + p_l;

    // B loader: float4 columns
    int bc4 = (tid & 31) * 4;
    int bk  = tid >> 5;                  // 0..7

    const int NT = CIN / 16;             // 16 k-tiles

    // ---- prologue: load tile 0 directly into buffer 0 ----
    #pragma unroll
    for (int j = 0; j < 8; j++)
        sA[0][lkq * 8 + j][lr] = xrow[(size_t)(lkq * 8 + j) * P_];
    #pragma unroll
    for (int j = 0; j < 2; j++)
        *(float4*)&sB[0][bk + j * 8][bc4] =
            *(const float4*)&Wm[(size_t)(bk + j * 8) * 256 + colBase + bc4];
    __syncthreads();

    float acc[8][8] = {};
    int buf = 0;
    for (int t = 0; t < NT; t++) {
        // ---- issue LDGs for tile t+1 (held in registers during compute) ----
        float  ra[8];
        float4 rb[2];
        if (t + 1 < NT) {
            int k0 = (t + 1) * 16;
            #pragma unroll
            for (int j = 0; j < 8; j++)
                ra[j] = xrow[(size_t)(k0 + lkq * 8 + j) * P_];
            #pragma unroll
            for (int j = 0; j < 2; j++)
                rb[j] = *(const float4*)&Wm[(size_t)(k0 + bk + j * 8) * 256 + colBase + bc4];
        }
        // ---- compute on current buffer ----
        #pragma unroll
        for (int k = 0; k < 16; k++) {
            float a[8], bb[8];
            *(float4*)&a[0]  = *(const float4*)&sA[buf][k][ty * 8];
            *(float4*)&a[4]  = *(const float4*)&sA[buf][k][ty * 8 + 4];
            *(float4*)&bb[0] = *(const float4*)&sB[buf][k][tx * 8];
            *(float4*)&bb[4] = *(const float4*)&sB[buf][k][tx * 8 + 4];
            #pragma unroll
            for (int i = 0; i < 8; i++)
                #pragma unroll
                for (int j = 0; j < 8; j++)
                    acc[i][j] += a[i] * bb[j];
        }
        // ---- stage tile t+1 into the other buffer ----
        if (t + 1 < NT) {
            int nxt = buf ^ 1;
            #pragma unroll
            for (int j = 0; j < 8; j++)
                sA[nxt][lkq * 8 + j][lr] = ra[j];
            #pragma unroll
            for (int j = 0; j < 2; j++)
                *(float4*)&sB[nxt][bk + j * 8][bc4] = rb[j];
            __syncthreads();
            buf = nxt;
        }
    }

    // attention vectors for this thread's 8 columns (flat [256] == [2,128])
    float as_r[8], ad_r[8];
    #pragma unroll
    for (int j = 0; j < 8; j++) {
        as_r[j] = att_src[colBase + tx * 8 + j];
        ad_r[j] = att_dst[colBase + tx * 8 + j];
    }
    int head = colBase >> 7;

    #pragma unroll
    for (int i = 0; i < 8; i++) {
        size_t n = rowBase + ty * 8 + i;
        float* hw = g_h + n * 256 + colBase + tx * 8;
        *(float4*)&hw[0] = make_float4(acc[i][0], acc[i][1], acc[i][2], acc[i][3]);
        *(float4*)&hw[4] = make_float4(acc[i][4], acc[i][5], acc[i][6], acc[i][7]);
        float s = 0.f, d = 0.f;
        #pragma unroll
        for (int j = 0; j < 8; j++) { s += acc[i][j] * as_r[j]; d += acc[i][j] * ad_r[j]; }
        #pragma unroll
        for (int off = 8; off; off >>= 1) {
            s += __shfl_down_sync(0xffffffffu, s, off, 16);
            d += __shfl_down_sync(0xffffffffu, d, off, 16);
        }
        if (tx == 0) {
            g_as[n * 2 + head] = s;
            g_ad[n * 2 + head] = d;
        }
    }
}

// ---------------- Kernel B: space attention softmax + gather-accumulate ----------
// Incoming edges of node n are exactly edges [9n, 9n+9) plus self-loop.
__global__ void __launch_bounds__(128) space_att(const int* __restrict__ ei,
                                                 const float* __restrict__ bias) {
    int n = blockIdx.x;
    int tid = threadIdx.x;            // 128
    __shared__ int   ssrc[10];
    __shared__ float ev[10][2];
    __shared__ float alpha[10][2];
    if (tid < 10) ssrc[tid] = (tid < 9) ? ei[n * 9 + tid] : n;
    __syncthreads();
    if (tid < 20) {
        int k = tid >> 1, hd = tid & 1;
        int s = ssrc[k];
        float e = g_as[s * 2 + hd] + g_ad[n * 2 + hd];
        ev[k][hd] = (e > 0.f) ? e : 0.2f * e;   // leaky_relu(0.2)
    }
    __syncthreads();
    if (tid < 2) {
        float m = -1e30f;
        #pragma unroll
        for (int k = 0; k < 10; k++) m = fmaxf(m, ev[k][tid]);
        float tmp[10]; float s = 0.f;
        #pragma unroll
        for (int k = 0; k < 10; k++) { tmp[k] = expf(ev[k][tid] - m); s += tmp[k]; }
        float inv = 1.f / (s + 1e-16f);
        #pragma unroll
        for (int k = 0; k < 10; k++) alpha[k][tid] = tmp[k] * inv;
    }
    __syncthreads();
    int c0 = tid, c1 = tid + 128;
    float a0 = 0.f, a1 = 0.f;
    #pragma unroll
    for (int k = 0; k < 10; k++) {
        const float* hr = g_h + (size_t)ssrc[k] * 256;
        a0 += alpha[k][0] * hr[c0];
        a1 += alpha[k][1] * hr[c1];
    }
    size_t base = (size_t)n * 256;
    g_xs[base + c0] = a0 + bias[c0];
    g_xs[base + c1] = a1 + bias[c1];
}

// ---------------- Kernel B2: per-image mean pool phase 1 -------------------------
// (64 images x 8 chunks) blocks, each sums 72 rows of g_xs. Phase 2 is fused
// into view_lin (deterministic fixed-order sums, no atomics).
__global__ void __launch_bounds__(256) pool_partial() {
    int b = blockIdx.x, chunk = blockIdx.y, c = threadIdx.x;
    const float* base = g_xs + ((size_t)b * P_ + chunk * 72) * 256 + c;
    float acc = 0.f;
    #pragma unroll 8
    for (int p = 0; p < 72; p++) acc += base[(size_t)p * 256];
    g_pp[(b * 8 + chunk) * 256 + c] = acc;
}

// ---------------- Kernel C1: pool finalize + view linear + attn logits -----------
__global__ void __launch_bounds__(256) view_lin(const float* __restrict__ Wv,
                                                const float* __restrict__ asv,
                                                const float* __restrict__ adv) {
    int b = blockIdx.x, j = threadIdx.x;
    __shared__ float se[256];
    __shared__ float red[256];
    {   // fused pool phase 2: emb[b][j] = (sum of 8 partials) / 576
        float acc = 0.f;
        #pragma unroll
        for (int k = 0; k < 8; k++) acc += g_pp[(b * 8 + k) * 256 + j];
        se[j] = acc * (1.0f / P_);
    }
    __syncthreads();
    float acc = 0.f;
    #pragma unroll 8
    for (int k = 0; k < 256; k++) acc += se[k] * Wv[k * 256 + j];
    g_hv[b * 256 + j] = acc;
    red[j] = acc * asv[j];
    __syncthreads();
    for (int s = 128; s; s >>= 1) { if (j < s) red[j] += red[j + s]; __syncthreads(); }
    if (j == 0) g_avs[b] = red[0];
    __syncthreads();
    red[j] = acc * adv[j];
    __syncthreads();
    for (int s = 128; s; s >>= 1) { if (j < s) red[j] += red[j + s]; __syncthreads(); }
    if (j == 0) g_avd[b] = red[0];
}

// ---------------- Kernel C2: view attention (only dst < 64 consumed) -------------
// Generic edge scan: block i gathers its incoming edges, softmax, accumulate.
// h/logits for node s equal those of s % 64 (emb_all[i] = emb[i % 64]).
__global__ void __launch_bounds__(256) view_att(const int* __restrict__ ei, int E,
                                                const float* __restrict__ biasv) {
    int i = blockIdx.x;               // dst node < 64
    int tid = threadIdx.x;
    __shared__ int cnt;
    __shared__ int srcs[128];
    __shared__ float al[128];
    if (tid == 0) { cnt = 1; srcs[0] = i; }   // self-loop
    __syncthreads();
    for (int e = tid; e < E; e += 256) {
        if (ei[E + e] == i) {
            int pos = atomicAdd(&cnt, 1);
            if (pos < 128) srcs[pos] = ei[e];
        }
    }
    __syncthreads();
    int C = cnt < 128 ? cnt : 128;
    if (tid == 0) {
        float ad = g_avd[i];
        float m = -1e30f;
        float tmp[128];
        for (int j = 0; j < C; j++) {
            float e = g_avs[srcs[j] & 63] + ad;   // srcs[j] % 64
            e = (e > 0.f) ? e : 0.2f * e;
            tmp[j] = e; m = fmaxf(m, e);
        }
        float s = 0.f;
        for (int j = 0; j < C; j++) { tmp[j] = expf(tmp[j] - m); s += tmp[j]; }
        float inv = 1.f / (s + 1e-16f);
        for (int j = 0; j < C; j++) al[j] = tmp[j] * inv;
    }
    __syncthreads();
    float acc = 0.f;
    for (int j = 0; j < C; j++)
        acc += al[j] * g_hv[(srcs[j] & 63) * 256 + tid];
    g_feat[i * 256 + tid] = acc + biasv[tid];
}

// ---------------- Kernel D: final combine, float4, raw row-major write -----------
// out flat index = b*P*C + p*C + c (reference's reshape is a raw reinterpret).
// Grid: (144 p-quarters, 64 images); thread c covers 4 floats.
__global__ void __launch_bounds__(256) combine(float* __restrict__ out) {
    int b = blockIdx.y;
    int q = blockIdx.x;               // 144 quarters of (P*256/4)/256
    size_t base4 = ((size_t)b * P_ * 256) / 4 + (size_t)q * 256 + threadIdx.x;
    int c4 = (q & 63) * 4 + 0;        // wrong if P*256/4 not multiple... compute directly:
    // flat float4 index within image: f4 = q*256 + tid; column = (f4*4) & 255
    size_t f4 = (size_t)q * 256 + threadIdx.x;
    int col4 = (int)((f4 * 4) & 255);
    const float4* xs4 = (const float4*)g_xs;
    const float4* ft4 = (const float4*)g_feat;
    float4 a = xs4[base4];
    float4 f = ft4[(b * 256 + col4) / 4];
    float4 r;
    r.x = 0.5f * a.x + 0.5f * f.x;
    r.y = 0.5f * a.y + 0.5f * f.y;
    r.z = 0.5f * a.z + 0.5f * f.z;
    r.w = 0.5f * a.w + 0.5f * f.w;
    ((float4*)out)[base4] = r;
    (void)c4;
}

// ---------------- launcher -------------------------------------------------------
extern "C" void kernel_launch(void* const* d_in, const int* in_sizes, int n_in,
                              void* d_out, int out_size) {
    const float* x        = (const float*)d_in[0];
    const int*   ei_space = (const int*)  d_in[3];
    const int*   ei_view  = (const int*)  d_in[4];
    const float* W_space  = (const float*)d_in[5];
    const float* att_src_s= (const float*)d_in[6];
    const float* att_dst_s= (const float*)d_in[7];
    const float* bias_s   = (const float*)d_in[8];
    const float* W_view   = (const float*)d_in[9];
    const float* att_src_v= (const float*)d_in[10];
    const float* att_dst_v= (const float*)d_in[11];
    const float* bias_v   = (const float*)d_in[12];
    float* out = (float*)d_out;
    int E_view = in_sizes[4] / 2;

    dim3 gA(N_NODES / 128, 2);
    gemm_space<<<gA, 256>>>(x, W_space, att_src_s, att_dst_s);
    space_att<<<N_NODES, 128>>>(ei_space, bias_s);
    pool_partial<<<dim3(B0_, 8), 256>>>();
    view_lin<<<B0_, 256>>>(W_view, att_src_v, att_dst_v);
    view_att<<<B0_, 256>>>(ei_view, E_view, bias_v);
    // per image: P*256/4 = 36864 float4s = 144 blocks of 256 threads
    combine<<<dim3(144, B0_), 256>>>(out);
}

// round 6
// speedup vs baseline: 1.4457x; 1.4457x over previous
#include <cuda_runtime.h>

#define HH 24
#define WW 24
#define P_ 576
#define B0_ 64
#define B_ 128
#define CIN 256
#define HID 128
#define OUTC 256
#define KNN 9
#define N_NODES (B0_*P_)   // 36864
#define SAS 136            // smem row stride (words): (k*136+m)%32 = k*8+m -> conflict-free frags

// ---------------- scratch (static device globals; no allocation) ----------------
__device__ float g_h [N_NODES*256];   // space linear output [N, 2*128]
__device__ float g_as[N_NODES*2];     // per-node attn src logits (2 heads)
__device__ float g_ad[N_NODES*2];     // per-node attn dst logits
__device__ float g_xs[N_NODES*256];   // x_space
__device__ float g_pp [B0_*8*256];    // pool partials [b, chunk, c]
__device__ float g_emb[B0_*256];      // pooled per-image embedding
__device__ float g_hv [B0_*256];      // view linear output (64 distinct rows)
__device__ float g_avs[B0_];          // view attn src logits
__device__ float g_avd[B0_];          // view attn dst logits
__device__ float g_feat[B0_*256];     // view GAT output (only first 64 needed)

__device__ __forceinline__ float to_tf32(float x) {
    unsigned u;
    asm("cvt.rna.tf32.f32 %0, %1;" : "=r"(u) : "f"(x));
    return __uint_as_float(u);
}

__device__ __forceinline__ void mma_tf32(float* c, float a0, float a1, float a2, float a3,
                                         float b0, float b1) {
    asm volatile(
        "mma.sync.aligned.m16n8k8.row.col.f32.tf32.tf32.f32 "
        "{%0,%1,%2,%3}, {%4,%5,%6,%7}, {%8,%9}, {%0,%1,%2,%3};"
        : "+f"(c[0]), "+f"(c[1]), "+f"(c[2]), "+f"(c[3])
        : "r"(__float_as_uint(a0)), "r"(__float_as_uint(a1)),
          "r"(__float_as_uint(a2)), "r"(__float_as_uint(a3)),
          "r"(__float_as_uint(b0)), "r"(__float_as_uint(b1)));
}

// ---------------- Kernel A: tf32 gather-GEMM  h = node @ W_space -----------------
// node[n,c] = x[b, c, p] (n = b*576 + p). Block tile 128x128, K-tiles of 16,
// double-buffered register-prefetch staging, tf32 conversion at STS time.
// 8 warps = 2(M) x 4(N); warp tile 64x32 = 4x4 m16n8k8 mma tiles.
__global__ void __launch_bounds__(256, 2)
gemm_space(const float* __restrict__ x, const float* __restrict__ Wm) {
    __shared__ float sA[2][16][SAS];
    __shared__ float sB[2][16][SAS];
    int tid  = threadIdx.x;
    int lane = tid & 31, wid = tid >> 5;
    int warp_m = wid >> 2, warp_n = wid & 3;
    int gid = lane >> 2, tig = lane & 3;
    int rowBase = blockIdx.x * 128;      // 288 blocks
    int colBase = blockIdx.y * 128;      // 2 blocks

    // A loader: thread owns tile-row lr, k-quadrant lkq (8 k's each)
    int lr  = tid & 127;
    int lkq = tid >> 7;
    int n_l = rowBase + lr;
    int b_l = n_l / P_;
    int p_l = n_l - b_l * P_;
    const float* xrow = x + (size_t)b_l * (CIN * P_) + p_l;
    // B loader: float4 columns
    int bc4 = (tid & 31) * 4;
    int bk  = tid >> 5;                  // 0..7

    // ---- prologue: tile 0 into buffer 0 (tf32-converted) ----
    #pragma unroll
    for (int j = 0; j < 8; j++)
        sA[0][lkq * 8 + j][lr] = to_tf32(xrow[(size_t)(lkq * 8 + j) * P_]);
    #pragma unroll
    for (int j = 0; j < 2; j++) {
        float4 v = *(const float4*)&Wm[(size_t)(bk + j * 8) * 256 + colBase + bc4];
        float* dst = &sB[0][bk + j * 8][bc4];
        dst[0] = to_tf32(v.x); dst[1] = to_tf32(v.y);
        dst[2] = to_tf32(v.z); dst[3] = to_tf32(v.w);
    }
    __syncthreads();

    float acc[4][4][4];
    #pragma unroll
    for (int i = 0; i < 4; i++)
        #pragma unroll
        for (int j = 0; j < 4; j++)
            #pragma unroll
            for (int r = 0; r < 4; r++) acc[i][j][r] = 0.f;

    const int NT = CIN / 16;             // 16 k-tiles
    int buf = 0;
    for (int t = 0; t < NT; t++) {
        float  ra[8];
        float4 rb[2];
        if (t + 1 < NT) {
            int k0 = (t + 1) * 16;
            #pragma unroll
            for (int j = 0; j < 8; j++)
                ra[j] = xrow[(size_t)(k0 + lkq * 8 + j) * P_];
            #pragma unroll
            for (int j = 0; j < 2; j++)
                rb[j] = *(const float4*)&Wm[(size_t)(k0 + bk + j * 8) * 256 + colBase + bc4];
        }
        // ---- compute: two k8 sub-steps ----
        #pragma unroll
        for (int ks = 0; ks < 16; ks += 8) {
            float bf[4][2];
            #pragma unroll
            for (int nt = 0; nt < 4; nt++) {
                int c = warp_n * 32 + nt * 8 + gid;
                bf[nt][0] = sB[buf][ks + tig][c];
                bf[nt][1] = sB[buf][ks + tig + 4][c];
            }
            #pragma unroll
            for (int mt = 0; mt < 4; mt++) {
                int r = warp_m * 64 + mt * 16 + gid;
                float a0 = sA[buf][ks + tig][r];
                float a1 = sA[buf][ks + tig][r + 8];
                float a2 = sA[buf][ks + tig + 4][r];
                float a3 = sA[buf][ks + tig + 4][r + 8];
                #pragma unroll
                for (int nt = 0; nt < 4; nt++)
                    mma_tf32(acc[mt][nt], a0, a1, a2, a3, bf[nt][0], bf[nt][1]);
            }
        }
        // ---- stage tile t+1 ----
        if (t + 1 < NT) {
            int nxt = buf ^ 1;
            #pragma unroll
            for (int j = 0; j < 8; j++)
                sA[nxt][lkq * 8 + j][lr] = to_tf32(ra[j]);
            #pragma unroll
            for (int j = 0; j < 2; j++) {
                float* dst = &sB[nxt][bk + j * 8][bc4];
                dst[0] = to_tf32(rb[j].x); dst[1] = to_tf32(rb[j].y);
                dst[2] = to_tf32(rb[j].z); dst[3] = to_tf32(rb[j].w);
            }
            __syncthreads();
            buf = nxt;
        }
    }

    // ---- epilogue: write g_h (float2 per fragment half) ----
    #pragma unroll
    for (int mt = 0; mt < 4; mt++) {
        int r0 = rowBase + warp_m * 64 + mt * 16 + gid;
        #pragma unroll
        for (int nt = 0; nt < 4; nt++) {
            int c = colBase + warp_n * 32 + nt * 8 + 2 * tig;
            *(float2*)&g_h[(size_t)r0 * 256 + c]       = make_float2(acc[mt][nt][0], acc[mt][nt][1]);
            *(float2*)&g_h[(size_t)(r0 + 8) * 256 + c] = make_float2(acc[mt][nt][2], acc[mt][nt][3]);
        }
    }
}

// ---------------- Kernel A2: per-node attention logits ---------------------------
// att_src_space/att_dst_space are [2,128] -> flat index == channel index.
__global__ void __launch_bounds__(256) att_dots(const float* __restrict__ att_src,
                                                const float* __restrict__ att_dst) {
    int warp = (blockIdx.x * blockDim.x + threadIdx.x) >> 5;
    int lane = threadIdx.x & 31;
    if (warp >= N_NODES) return;
    const float* hr = g_h + (size_t)warp * 256;
    float s0 = 0.f, s1 = 0.f, d0 = 0.f, d1 = 0.f;
    #pragma unroll
    for (int i = 0; i < 8; i++) {
        int c = lane + i * 32;
        float hv = hr[c];
        float as = att_src[c];
        float ad = att_dst[c];
        if (i < 4) { s0 += hv * as; d0 += hv * ad; }
        else       { s1 += hv * as; d1 += hv * ad; }
    }
    #pragma unroll
    for (int off = 16; off; off >>= 1) {
        s0 += __shfl_down_sync(0xffffffffu, s0, off);
        s1 += __shfl_down_sync(0xffffffffu, s1, off);
        d0 += __shfl_down_sync(0xffffffffu, d0, off);
        d1 += __shfl_down_sync(0xffffffffu, d1, off);
    }
    if (lane == 0) {
        g_as[warp * 2 + 0] = s0; g_as[warp * 2 + 1] = s1;
        g_ad[warp * 2 + 0] = d0; g_ad[warp * 2 + 1] = d1;
    }
}

// ---------------- Kernel B: space attention, 4 nodes per block -------------------
// Incoming edges of node n are exactly edges [9n, 9n+9) plus self-loop.
// 4 consecutive nodes share ~6/10 kNN neighbors -> L1 reuse of g_h rows.
__global__ void __launch_bounds__(512) space_att(const int* __restrict__ ei,
                                                 const float* __restrict__ bias) {
    int g   = threadIdx.x >> 7;       // subgroup 0..3
    int tid = threadIdx.x & 127;
    int n   = blockIdx.x * 4 + g;     // 9216 blocks
    __shared__ int   ssrc[4][10];
    __shared__ float ev[4][10][2];
    __shared__ float alpha[4][10][2];
    if (tid < 10) ssrc[g][tid] = (tid < 9) ? ei[n * 9 + tid] : n;
    __syncthreads();
    if (tid < 20) {
        int k = tid >> 1, hd = tid & 1;
        int s = ssrc[g][k];
        float e = g_as[s * 2 + hd] + g_ad[n * 2 + hd];
        ev[g][k][hd] = (e > 0.f) ? e : 0.2f * e;   // leaky_relu(0.2)
    }
    __syncthreads();
    if (tid < 2) {
        float m = -1e30f;
        #pragma unroll
        for (int k = 0; k < 10; k++) m = fmaxf(m, ev[g][k][tid]);
        float tmp[10]; float s = 0.f;
        #pragma unroll
        for (int k = 0; k < 10; k++) { tmp[k] = expf(ev[g][k][tid] - m); s += tmp[k]; }
        float inv = 1.f / (s + 1e-16f);
        #pragma unroll
        for (int k = 0; k < 10; k++) alpha[g][k][tid] = tmp[k] * inv;
    }
    __syncthreads();
    int c0 = tid, c1 = tid + 128;
    float a0 = 0.f, a1 = 0.f;
    #pragma unroll
    for (int k = 0; k < 10; k++) {
        const float* hr = g_h + (size_t)ssrc[g][k] * 256;
        a0 += alpha[g][k][0] * hr[c0];
        a1 += alpha[g][k][1] * hr[c1];
    }
    size_t base = (size_t)n * 256;
    g_xs[base + c0] = a0 + bias[c0];
    g_xs[base + c1] = a1 + bias[c1];
}

// ---------------- Pool phase 1: (64 x 8) blocks, 72 rows each --------------------
__global__ void __launch_bounds__(256) pool_partial() {
    int b = blockIdx.x, chunk = blockIdx.y, c = threadIdx.x;
    const float* base = g_xs + ((size_t)b * P_ + chunk * 72) * 256 + c;
    float acc = 0.f;
    #pragma unroll 8
    for (int p = 0; p < 72; p++) acc += base[(size_t)p * 256];
    g_pp[(b * 8 + chunk) * 256 + c] = acc;
}
// ---------------- Pool phase 2 ---------------------------------------------------
__global__ void __launch_bounds__(256) pool_final() {
    int b = blockIdx.x, c = threadIdx.x;
    float acc = 0.f;
    #pragma unroll
    for (int k = 0; k < 8; k++) acc += g_pp[(b * 8 + k) * 256 + c];
    g_emb[b * 256 + c] = acc * (1.0f / P_);
}

// ---------------- Kernel C1: view linear, wide (64 x 8 blocks) -------------------
// Block (b, jc): 32 output cols, k-dim split over 8 thread groups + smem reduce.
__global__ void __launch_bounds__(256) view_gemv(const float* __restrict__ Wv) {
    int b = blockIdx.x, jc = blockIdx.y;
    int t = threadIdx.x;
    __shared__ float se[256];
    __shared__ float red[8][32];
    se[t] = g_emb[b * 256 + t];
    __syncthreads();
    int j  = jc * 32 + (t & 31);
    int kg = t >> 5;
    float acc = 0.f;
    #pragma unroll
    for (int i = 0; i < 32; i++) {
        int k = kg * 32 + i;
        acc += se[k] * Wv[k * 256 + j];
    }
    red[kg][t & 31] = acc;
    __syncthreads();
    if (t < 32) {
        float s = 0.f;
        #pragma unroll
        for (int k = 0; k < 8; k++) s += red[k][t];
        g_hv[b * 256 + jc * 32 + t] = s;
    }
}

// ---------------- Kernel C1b: view attention logits ------------------------------
__global__ void __launch_bounds__(256) view_logits(const float* __restrict__ asv,
                                                   const float* __restrict__ adv) {
    int b = blockIdx.x, t = threadIdx.x;
    __shared__ float red[256];
    float v = g_hv[b * 256 + t];
    red[t] = v * asv[t];
    __syncthreads();
    for (int s = 128; s; s >>= 1) { if (t < s) red[t] += red[t + s]; __syncthreads(); }
    if (t == 0) g_avs[b] = red[0];
    __syncthreads();
    red[t] = v * adv[t];
    __syncthreads();
    for (int s = 128; s; s >>= 1) { if (t < s) red[t] += red[t + s]; __syncthreads(); }
    if (t == 0) g_avd[b] = red[0];
}

// ---------------- Kernel C2: view attention (only dst < 64 consumed) -------------
__global__ void __launch_bounds__(256) view_att(const int* __restrict__ ei, int E,
                                                const float* __restrict__ biasv) {
    int i = blockIdx.x;               // dst node < 64
    int tid = threadIdx.x;
    __shared__ int cnt;
    __shared__ int srcs[128];
    __shared__ float al[128];
    if (tid == 0) { cnt = 1; srcs[0] = i; }   // self-loop
    __syncthreads();
    for (int e = tid; e < E; e += 256) {
        if (ei[E + e] == i) {
            int pos = atomicAdd(&cnt, 1);
            if (pos < 128) srcs[pos] = ei[e];
        }
    }
    __syncthreads();
    int C = cnt < 128 ? cnt : 128;
    if (tid == 0) {
        float ad = g_avd[i];
        float m = -1e30f;
        float tmp[128];
        for (int j = 0; j < C; j++) {
            float e = g_avs[srcs[j] & 63] + ad;   // srcs[j] % 64
            e = (e > 0.f) ? e : 0.2f * e;
            tmp[j] = e; m = fmaxf(m, e);
        }
        float s = 0.f;
        for (int j = 0; j < C; j++) { tmp[j] = expf(tmp[j] - m); s += tmp[j]; }
        float inv = 1.f / (s + 1e-16f);
        for (int j = 0; j < C; j++) al[j] = tmp[j] * inv;
    }
    __syncthreads();
    float acc = 0.f;
    for (int j = 0; j < C; j++)
        acc += al[j] * g_hv[(srcs[j] & 63) * 256 + tid];
    g_feat[i * 256 + tid] = acc + biasv[tid];
}

// ---------------- Kernel D: final combine, float4 --------------------------------
// out flat index = b*P*C + p*C + c (reference's reshape is a raw reinterpret).
__global__ void __launch_bounds__(256) combine(float* __restrict__ out) {
    int b = blockIdx.y;
    int q = blockIdx.x;               // 144 blocks of 256 float4s per image
    size_t f4   = (size_t)q * 256 + threadIdx.x;         // float4 idx within image
    size_t idx4 = ((size_t)b * P_ * 256) / 4 + f4;
    int col4 = (int)((f4 * 4) & 255);
    float4 a = ((const float4*)g_xs)[idx4];
    float4 f = ((const float4*)g_feat)[(b * 256 + col4) >> 2];
    float4 r;
    r.x = 0.5f * a.x + 0.5f * f.x;
    r.y = 0.5f * a.y + 0.5f * f.y;
    r.z = 0.5f * a.z + 0.5f * f.z;
    r.w = 0.5f * a.w + 0.5f * f.w;
    ((float4*)out)[idx4] = r;
}

// ---------------- launcher -------------------------------------------------------
extern "C" void kernel_launch(void* const* d_in, const int* in_sizes, int n_in,
                              void* d_out, int out_size) {
    const float* x        = (const float*)d_in[0];
    const int*   ei_space = (const int*)  d_in[3];
    const int*   ei_view  = (const int*)  d_in[4];
    const float* W_space  = (const float*)d_in[5];
    const float* att_src_s= (const float*)d_in[6];
    const float* att_dst_s= (const float*)d_in[7];
    const float* bias_s   = (const float*)d_in[8];
    const float* W_view   = (const float*)d_in[9];
    const float* att_src_v= (const float*)d_in[10];
    const float* att_dst_v= (const float*)d_in[11];
    const float* bias_v   = (const float*)d_in[12];
    float* out = (float*)d_out;
    int E_view = in_sizes[4] / 2;

    gemm_space<<<dim3(N_NODES / 128, 2), 256>>>(x, W_space);
    att_dots<<<N_NODES * 32 / 256, 256>>>(att_src_s, att_dst_s);
    space_att<<<N_NODES / 4, 512>>>(ei_space, bias_s);
    pool_partial<<<dim3(B0_, 8), 256>>>();
    pool_final<<<B0_, 256>>>();
    view_gemv<<<dim3(B0_, 8), 256>>>(W_view);
    view_logits<<<B0_, 256>>>(att_src_v, att_dst_v);
    view_att<<<B0_, 256>>>(ei_view, E_view, bias_v);
    combine<<<dim3(144, B0_), 256>>>(out);
}